// round 9
// baseline (speedup 1.0000x reference)
#include <cuda_runtime.h>
#include <cstdint>

#define NUSER 100000
#define NITEM 50000
#define NNODE 150000
#define DIM   64
#define FEATD 4096
#define HID   256
#define EMAX  1200000

// ---------------- scratch (device globals; no allocation allowed) ----------------
__device__ float g_H[(size_t)NITEM * HID];     // hidden after leaky   (51.2 MB)
__device__ float g_x[(size_t)NNODE * DIM];     // normalized x         (38.4 MB)
__device__ float g_h[(size_t)NNODE * DIM];     // conv1
__device__ int   g_cnt[NNODE];
__device__ int   g_scan[NNODE];
__device__ int   g_ptr[NNODE + 1];
__device__ int   g_cur[NNODE];
__device__ float g_dis[NNODE];
__device__ uint2 g_edge[EMAX];                 // (src, bits(dis[src]))
__device__ int   g_bsum[256];
__device__ int   g_boff[256];

// ---------------- helpers ----------------
__device__ __forceinline__ uint32_t cvt_tf32(float x) {
    uint32_t r;
    asm("cvt.rna.tf32.f32 %0, %1;" : "=r"(r) : "f"(x));
    return r;
}

__device__ __forceinline__ void mma8(float* c, const uint32_t* a, const uint32_t* b) {
    asm volatile(
        "mma.sync.aligned.m16n8k8.row.col.f32.tf32.tf32.f32 "
        "{%0,%1,%2,%3},{%4,%5,%6,%7},{%8,%9},{%0,%1,%2,%3};"
        : "+f"(c[0]), "+f"(c[1]), "+f"(c[2]), "+f"(c[3])
        : "r"(a[0]), "r"(a[1]), "r"(a[2]), "r"(a[3]), "r"(b[0]), "r"(b[1]));
}

__device__ __forceinline__ void cp16(void* dst, const void* src, bool valid) {
    uint32_t d = (uint32_t)__cvta_generic_to_shared(dst);
    int sz = valid ? 16 : 0;
    asm volatile("cp.async.cg.shared.global [%0], [%1], 16, %2;\n"
                 :: "r"(d), "l"(src), "r"(sz));
}

// ---------------- graph structure ----------------
__global__ void zero_k() {
    int i = blockIdx.x * blockDim.x + threadIdx.x;
    if (i < NNODE) g_cnt[i] = 0;
}

__global__ void count_k(const int* __restrict__ col, int E) {
    int e = blockIdx.x * blockDim.x + threadIdx.x;
    if (e < E) atomicAdd(&g_cnt[col[e]], 1);
}

__global__ void scan1_k() {
    __shared__ int s[1024];
    int t = threadIdx.x;
    int i = blockIdx.x * 1024 + t;
    int v = (i < NNODE) ? g_cnt[i] : 0;
    s[t] = v;
    __syncthreads();
    for (int off = 1; off < 1024; off <<= 1) {
        int x = (t >= off) ? s[t - off] : 0;
        __syncthreads();
        s[t] += x;
        __syncthreads();
    }
    if (i < NNODE) g_scan[i] = s[t];
    if (t == 1023) g_bsum[blockIdx.x] = s[1023];
}

__global__ void scan2_k(int nb) {
    __shared__ int s[256];
    int t = threadIdx.x;
    int v = (t < nb) ? g_bsum[t] : 0;
    s[t] = v;
    __syncthreads();
    for (int off = 1; off < 256; off <<= 1) {
        int x = (t >= off) ? s[t - off] : 0;
        __syncthreads();
        s[t] += x;
        __syncthreads();
    }
    if (t < nb) g_boff[t] = s[t] - v;  // exclusive
}

__global__ void scan3_k() {
    int t = threadIdx.x;
    int i = blockIdx.x * 1024 + t;
    if (i < NNODE) {
        int c = g_cnt[i];
        int excl = g_scan[i] - c + g_boff[blockIdx.x];
        g_ptr[i] = excl;
        g_cur[i] = excl;
        g_dis[i] = (c > 0) ? rsqrtf((float)c) : 0.f;
        if (i == NNODE - 1) g_ptr[NNODE] = excl + c;
    }
}

__global__ void scatter_k(const int* __restrict__ row, const int* __restrict__ col, int E) {
    int e = blockIdx.x * blockDim.x + threadIdx.x;
    if (e < E) {
        int c = col[e], r = row[e];
        int pos = atomicAdd(&g_cur[c], 1);
        g_edge[pos] = make_uint2((unsigned)r, __float_as_uint(g_dis[r]));
    }
}

// ---------------- GEMM1: g_H = leaky(feat @ W1 + b1) ----------------
// Block 128x128, 8 warps of 32x64, BK=32, 3-stage cp.async, 2 CTAs/SM.
#define G1_BM 128
#define G1_BN 128
#define G1_BK 32
#define G1_ST 3
#define G1_ASTR 36            // conflict-free A (bank = 4*lr+lc)
#define G1_BSTR 136           // 128+8: conflict-free B (bank = 8*lc+lr)
#define G1_STAGE_F (G1_BM * G1_ASTR + G1_BK * G1_BSTR)   // 8960 floats
#define G1_SMEM (G1_ST * G1_STAGE_F * 4)                 // 107520 B
#define G1_NK (FEATD / G1_BK)                            // 128

__global__ void __launch_bounds__(256, 2)
gemm1_k(const float* __restrict__ A, const float* __restrict__ B,
        const float* __restrict__ bias, float* __restrict__ C) {
    extern __shared__ float sm[];

    int tid = threadIdx.x, lane = tid & 31, wid = tid >> 5;
    int wm0 = (wid & 3) * 32;          // 4 M-warps
    int wn0 = (wid >> 2) * 64;         // 2 N-warps
    int m0 = blockIdx.y * G1_BM;
    int n0 = blockIdx.x * G1_BN;

    float acc[2][8][4];
#pragma unroll
    for (int i = 0; i < 2; i++)
#pragma unroll
        for (int j = 0; j < 8; j++)
#pragma unroll
            for (int k = 0; k < 4; k++) acc[i][j][k] = 0.f;

    auto loadTile = [&](int kt, int buf) {
        float* base = sm + buf * G1_STAGE_F;
#pragma unroll
        for (int i = 0; i < 4; i++) {            // A: 128x32 = 1024 vec4
            int v = tid + i * 256;
            int ar = v >> 3, ac = (v & 7) * 4;
            bool ok = (m0 + ar) < NITEM;
            cp16(&base[ar * G1_ASTR + ac],
                 A + (size_t)(m0 + ar) * FEATD + (size_t)kt * G1_BK + ac, ok);
        }
        float* bbase = base + G1_BM * G1_ASTR;
#pragma unroll
        for (int i = 0; i < 4; i++) {            // B: 32x128 = 1024 vec4
            int v = tid + i * 256;
            int br = v >> 5, bc = (v & 31) * 4;
            cp16(&bbase[br * G1_BSTR + bc],
                 B + (size_t)(kt * G1_BK + br) * HID + n0 + bc, true);
        }
        asm volatile("cp.async.commit_group;\n");
    };

    loadTile(0, 0);
    loadTile(1, 1);

    int lr = lane >> 2, lc = lane & 3;

    for (int kt = 0; kt < G1_NK; kt++) {
        int buf = kt % G1_ST;
        if (kt < G1_NK - 1) asm volatile("cp.async.wait_group 1;\n");
        else                asm volatile("cp.async.wait_group 0;\n");
        __syncthreads();   // stage kt ready; all warps done with stage being overwritten
        if (kt + 2 < G1_NK) loadTile(kt + 2, (kt + 2) % G1_ST);

        const float* As = sm + buf * G1_STAGE_F;
        const float* Bs = As + G1_BM * G1_ASTR;

#pragma unroll
        for (int ks = 0; ks < 4; ks++) {
            int k0 = ks * 8;
            uint32_t fa[2][4], fb[8][2];
#pragma unroll
            for (int mf = 0; mf < 2; mf++) {
                int r = wm0 + mf * 16 + lr;
                fa[mf][0] = __float_as_uint(As[r * G1_ASTR + k0 + lc]);
                fa[mf][1] = __float_as_uint(As[(r + 8) * G1_ASTR + k0 + lc]);
                fa[mf][2] = __float_as_uint(As[r * G1_ASTR + k0 + lc + 4]);
                fa[mf][3] = __float_as_uint(As[(r + 8) * G1_ASTR + k0 + lc + 4]);
            }
#pragma unroll
            for (int nf = 0; nf < 8; nf++) {
                int c = wn0 + nf * 8 + lr;
                fb[nf][0] = __float_as_uint(Bs[(k0 + lc) * G1_BSTR + c]);
                fb[nf][1] = __float_as_uint(Bs[(k0 + lc + 4) * G1_BSTR + c]);
            }
#pragma unroll
            for (int mf = 0; mf < 2; mf++)
#pragma unroll
                for (int nf = 0; nf < 8; nf++)
                    mma8(acc[mf][nf], fa[mf], fb[nf]);
        }
    }

    // epilogue: bias + leaky, float2 stores
#pragma unroll
    for (int mf = 0; mf < 2; mf++) {
#pragma unroll
        for (int nf = 0; nf < 8; nf++) {
            int cg = n0 + wn0 + nf * 8 + 2 * lc;
            float bv0 = bias[cg], bv1 = bias[cg + 1];
            int r = m0 + wm0 + mf * 16 + lr;

            float v0 = acc[mf][nf][0] + bv0;
            float v1 = acc[mf][nf][1] + bv1;
            v0 = v0 > 0.f ? v0 : 0.01f * v0;
            v1 = v1 > 0.f ? v1 : 0.01f * v1;
            if (r < NITEM) *(float2*)&C[(size_t)r * HID + cg] = make_float2(v0, v1);

            float v2 = acc[mf][nf][2] + bv0;
            float v3 = acc[mf][nf][3] + bv1;
            v2 = v2 > 0.f ? v2 : 0.01f * v2;
            v3 = v3 > 0.f ? v3 : 0.01f * v3;
            if (r + 8 < NITEM) *(float2*)&C[(size_t)(r + 8) * HID + cg] = make_float2(v2, v3);
        }
    }
}

// ---------------- legacy tf32 tensor-core GEMM (used for GEMM2) ----------------
template <int BN, int WTM, int WTN, int NWM, int NWN, int KTOT, int LDA, int LDB, int EPI, int BVEC>
__global__ void __launch_bounds__(256)
gemm_tf32(const float* __restrict__ A, const float* __restrict__ B,
          const float* __restrict__ bias, float* __restrict__ C, int M, int ldc) {
    constexpr int BM = 128, BK = 32;
    constexpr int ASTR = BK + 4;
    constexpr int BSTR = BN + 4;
    constexpr int MFRAG = WTM / 16, NFRAG = WTN / 8;
    constexpr int NK = KTOT / BK;

    extern __shared__ float smf[];
    float* smA = smf;
    float* smB = smf + 2 * BM * ASTR;

    int tid = threadIdx.x, lane = tid & 31, wid = tid >> 5;
    int wm0 = (wid % NWM) * WTM;
    int wn0 = (wid / NWM) * WTN;
    int m0 = blockIdx.y * BM, n0 = blockIdx.x * BN;

    float acc[MFRAG][NFRAG][4];
#pragma unroll
    for (int i = 0; i < MFRAG; i++)
#pragma unroll
        for (int j = 0; j < NFRAG; j++)
#pragma unroll
            for (int k = 0; k < 4; k++) acc[i][j][k] = 0.f;

    auto loadTile = [&](int kt, int buf) {
#pragma unroll
        for (int i = 0; i < 4; i++) {
            int v = tid + i * 256;
            int ar = v >> 3, ac = (v & 7) * 4;
            bool ok = (m0 + ar) < M;
            cp16(&smA[buf * BM * ASTR + ar * ASTR + ac],
                 A + (size_t)(m0 + ar) * LDA + (size_t)kt * BK + ac, ok);
        }
#pragma unroll
        for (int i = 0; i < BVEC; i++) {
            int v = tid + i * 256;
            int br = v / (BN / 4), bc = (v % (BN / 4)) * 4;
            cp16(&smB[buf * BK * BSTR + br * BSTR + bc],
                 B + (size_t)(kt * BK + br) * LDB + n0 + bc, true);
        }
        asm volatile("cp.async.commit_group;\n");
    };

    loadTile(0, 0);
    int lr = lane >> 2, lc = lane & 3;

    for (int kt = 0; kt < NK; kt++) {
        int buf = kt & 1;
        if (kt + 1 < NK) {
            loadTile(kt + 1, buf ^ 1);
            asm volatile("cp.async.wait_group 1;\n");
        } else {
            asm volatile("cp.async.wait_group 0;\n");
        }
        __syncthreads();

        const float* As = smA + buf * BM * ASTR;
        const float* Bs = smB + buf * BK * BSTR;
#pragma unroll
        for (int ks = 0; ks < 4; ks++) {
            int k0 = ks * 8;
            uint32_t af[MFRAG][4], bf[NFRAG][2];
#pragma unroll
            for (int mf = 0; mf < MFRAG; mf++) {
                int r = wm0 + mf * 16 + lr;
                af[mf][0] = cvt_tf32(As[r * ASTR + k0 + lc]);
                af[mf][1] = cvt_tf32(As[(r + 8) * ASTR + k0 + lc]);
                af[mf][2] = cvt_tf32(As[r * ASTR + k0 + lc + 4]);
                af[mf][3] = cvt_tf32(As[(r + 8) * ASTR + k0 + lc + 4]);
            }
#pragma unroll
            for (int nf = 0; nf < NFRAG; nf++) {
                int c = wn0 + nf * 8 + lr;
                bf[nf][0] = cvt_tf32(Bs[(k0 + lc) * BSTR + c]);
                bf[nf][1] = cvt_tf32(Bs[(k0 + lc + 4) * BSTR + c]);
            }
#pragma unroll
            for (int mf = 0; mf < MFRAG; mf++)
#pragma unroll
                for (int nf = 0; nf < NFRAG; nf++)
                    mma8(acc[mf][nf], af[mf], bf[nf]);
        }
        __syncthreads();
    }

#pragma unroll
    for (int mf = 0; mf < MFRAG; mf++) {
#pragma unroll
        for (int nf = 0; nf < NFRAG; nf++) {
            int cg = n0 + wn0 + nf * 8 + 2 * lc;
            float bv0 = bias[cg], bv1 = bias[cg + 1];
            int r = m0 + wm0 + mf * 16 + lr;

            float v0 = acc[mf][nf][0] + bv0;
            float v1 = acc[mf][nf][1] + bv1;
            if (EPI == 0) {
                v0 = v0 > 0.f ? v0 : 0.01f * v0;
                v1 = v1 > 0.f ? v1 : 0.01f * v1;
            }
            if (r < M) *(float2*)&C[(size_t)r * ldc + cg] = make_float2(v0, v1);

            float v2 = acc[mf][nf][2] + bv0;
            float v3 = acc[mf][nf][3] + bv1;
            if (EPI == 0) {
                v2 = v2 > 0.f ? v2 : 0.01f * v2;
                v3 = v3 > 0.f ? v3 : 0.01f * v3;
            }
            if (r + 8 < M) *(float2*)&C[(size_t)(r + 8) * ldc + cg] = make_float2(v2, v3);
        }
    }
}

// ---------------- normalize rows of x ----------------
__global__ void normalize_k(const float* __restrict__ pref) {
    int warp = (blockIdx.x * blockDim.x + threadIdx.x) >> 5;
    if (warp >= NNODE) return;
    int lane = threadIdx.x & 31;
    const float* src = (warp < NUSER) ? (pref + (size_t)warp * DIM)
                                      : (g_x + (size_t)warp * DIM);
    float v0 = src[lane], v1 = src[lane + 32];
    float s = v0 * v0 + v1 * v1;
#pragma unroll
    for (int o = 16; o; o >>= 1) s += __shfl_xor_sync(0xffffffffu, s, o);
    float inv = 1.0f / fmaxf(sqrtf(s), 1e-12f);
    g_x[(size_t)warp * DIM + lane] = v0 * inv;
    g_x[(size_t)warp * DIM + lane + 32] = v1 * inv;
}

// ---------------- warp-per-node gather convs ----------------
__global__ void gather1_k() {
    int warp = (blockIdx.x * blockDim.x + threadIdx.x) >> 5;
    if (warp >= NNODE) return;
    int lane = threadIdx.x & 31;
    int beg = g_ptr[warp], end = g_ptr[warp + 1];
    float a0 = 0.f, a1 = 0.f;
    for (int k = beg; k < end; k++) {
        uint2 e = g_edge[k];
        float c = __uint_as_float(e.y);
        const float* xs = g_x + (size_t)e.x * DIM;
        a0 += c * xs[lane];
        a1 += c * xs[lane + 32];
    }
    float dn = g_dis[warp];
    g_h[(size_t)warp * DIM + lane] = a0 * dn;
    g_h[(size_t)warp * DIM + lane + 32] = a1 * dn;
}

// conv2 fused with finalize: out = x + h + h1
__global__ void gather2_k(float* __restrict__ out) {
    int warp = (blockIdx.x * blockDim.x + threadIdx.x) >> 5;
    if (warp >= NNODE) return;
    int lane = threadIdx.x & 31;
    int beg = g_ptr[warp], end = g_ptr[warp + 1];
    float a0 = 0.f, a1 = 0.f;
    for (int k = beg; k < end; k++) {
        uint2 e = g_edge[k];
        float c = __uint_as_float(e.y);
        const float* xs = g_h + (size_t)e.x * DIM;
        a0 += c * xs[lane];
        a1 += c * xs[lane + 32];
    }
    float dn = g_dis[warp];
    size_t idx = (size_t)warp * DIM + lane;
    out[idx]      = g_x[idx]      + g_h[idx]      + a0 * dn;
    out[idx + 32] = g_x[idx + 32] + g_h[idx + 32] + a1 * dn;
}

// ---------------- host ----------------
extern "C" void kernel_launch(void* const* d_in, const int* in_sizes, int n_in,
                              void* d_out, int out_size) {
    const int*   ei   = (const int*)d_in[0];
    const float* feat = (const float*)d_in[1];
    const float* pref = (const float*)d_in[2];
    const float* W1   = (const float*)d_in[3];
    const float* b1   = (const float*)d_in[4];
    const float* W2   = (const float*)d_in[5];
    const float* b2   = (const float*)d_in[6];
    float* out = (float*)d_out;

    int E = in_sizes[0] / 2;
    const int* row = ei;
    const int* col = ei + E;

    float *pH = nullptr, *pX = nullptr;
    cudaGetSymbolAddress((void**)&pH, g_H);
    cudaGetSymbolAddress((void**)&pX, g_x);

    auto g2 = gemm_tf32<64, 32, 32, 4, 2, 256, 256, 64, 1, 2>;
    const int SMEM2 = (2 * 128 * 36 + 2 * 32 * 68) * 4;  // 54272
    cudaFuncSetAttribute(g2, cudaFuncAttributeMaxDynamicSharedMemorySize, SMEM2);
    cudaFuncSetAttribute(gemm1_k, cudaFuncAttributeMaxDynamicSharedMemorySize, G1_SMEM);

    // graph structure (+ GEMM1 placed 4th so ncu's profiled slot lands on it)
    zero_k<<<(NNODE + 255) / 256, 256>>>();
    count_k<<<(E + 255) / 256, 256>>>(col, E);
    scan1_k<<<147, 1024>>>();
    gemm1_k<<<dim3(2, (NITEM + G1_BM - 1) / G1_BM), 256, G1_SMEM>>>(feat, W1, b1, pH);
    scan2_k<<<1, 256>>>(147);
    scan3_k<<<147, 1024>>>();
    scatter_k<<<(E + 255) / 256, 256>>>(row, col, E);

    // item MLP tail
    g2<<<dim3(1, 391), 256, SMEM2>>>(pH, W2, b2, pX + (size_t)NUSER * DIM, NITEM, DIM);

    // normalize + 2 convs (conv2 fused with finalize)
    int warpBlocks = (NNODE * 32 + 255) / 256;
    normalize_k<<<warpBlocks, 256>>>(pref);
    gather1_k<<<warpBlocks, 256>>>();
    gather2_k<<<warpBlocks, 256>>>(out);

    // second output = preference
    if (out_size >= NNODE * DIM + NUSER * DIM) {
        cudaMemcpyAsync(out + (size_t)NNODE * DIM, pref,
                        (size_t)NUSER * DIM * sizeof(float),
                        cudaMemcpyDeviceToDevice);
    }
}

// round 10
// speedup vs baseline: 1.0515x; 1.0515x over previous
#include <cuda_runtime.h>
#include <cstdint>

#define NUSER 100000
#define NITEM 50000
#define NNODE 150000
#define DIM   64
#define FEATD 4096
#define HID   256
#define EMAX  1200000

// ---------------- scratch (device globals; no allocation allowed) ----------------
__device__ float g_x[(size_t)NNODE * DIM];     // normalized x         (38.4 MB)
__device__ float g_h[(size_t)NNODE * DIM];     // conv1
__device__ int   g_cnt[NNODE];
__device__ int   g_scan[NNODE];
__device__ int   g_ptr[NNODE + 1];
__device__ int   g_cur[NNODE];
__device__ float g_dis[NNODE];
__device__ uint2 g_edge[EMAX];                 // (src, bits(dis[src]))
__device__ int   g_bsum[256];
__device__ int   g_boff[256];

// ---------------- helpers ----------------
__device__ __forceinline__ void mma8(float* c, const uint32_t* a, const uint32_t* b) {
    asm volatile(
        "mma.sync.aligned.m16n8k8.row.col.f32.tf32.tf32.f32 "
        "{%0,%1,%2,%3},{%4,%5,%6,%7},{%8,%9},{%0,%1,%2,%3};"
        : "+f"(c[0]), "+f"(c[1]), "+f"(c[2]), "+f"(c[3])
        : "r"(a[0]), "r"(a[1]), "r"(a[2]), "r"(a[3]), "r"(b[0]), "r"(b[1]));
}

__device__ __forceinline__ void cp16(void* dst, const void* src, bool valid) {
    uint32_t d = (uint32_t)__cvta_generic_to_shared(dst);
    int sz = valid ? 16 : 0;
    asm volatile("cp.async.cg.shared.global [%0], [%1], 16, %2;\n"
                 :: "r"(d), "l"(src), "r"(sz));
}

// ---------------- graph structure ----------------
__global__ void zero_k() {
    int i = blockIdx.x * blockDim.x + threadIdx.x;
    if (i < NNODE) g_cnt[i] = 0;
}

__global__ void count_k(const int* __restrict__ col, int E) {
    int e = blockIdx.x * blockDim.x + threadIdx.x;
    if (e < E) atomicAdd(&g_cnt[col[e]], 1);
}

__global__ void scan1_k() {
    __shared__ int s[1024];
    int t = threadIdx.x;
    int i = blockIdx.x * 1024 + t;
    int v = (i < NNODE) ? g_cnt[i] : 0;
    s[t] = v;
    __syncthreads();
    for (int off = 1; off < 1024; off <<= 1) {
        int x = (t >= off) ? s[t - off] : 0;
        __syncthreads();
        s[t] += x;
        __syncthreads();
    }
    if (i < NNODE) g_scan[i] = s[t];
    if (t == 1023) g_bsum[blockIdx.x] = s[1023];
}

__global__ void scan2_k(int nb) {
    __shared__ int s[256];
    int t = threadIdx.x;
    int v = (t < nb) ? g_bsum[t] : 0;
    s[t] = v;
    __syncthreads();
    for (int off = 1; off < 256; off <<= 1) {
        int x = (t >= off) ? s[t - off] : 0;
        __syncthreads();
        s[t] += x;
        __syncthreads();
    }
    if (t < nb) g_boff[t] = s[t] - v;  // exclusive
}

__global__ void scan3_k() {
    int t = threadIdx.x;
    int i = blockIdx.x * 1024 + t;
    if (i < NNODE) {
        int c = g_cnt[i];
        int excl = g_scan[i] - c + g_boff[blockIdx.x];
        g_ptr[i] = excl;
        g_cur[i] = excl;
        g_dis[i] = (c > 0) ? rsqrtf((float)c) : 0.f;
        if (i == NNODE - 1) g_ptr[NNODE] = excl + c;
    }
}

__global__ void scatter_k(const int* __restrict__ row, const int* __restrict__ col, int E) {
    int e = blockIdx.x * blockDim.x + threadIdx.x;
    if (e < E) {
        int c = col[e], r = row[e];
        int pos = atomicAdd(&g_cur[c], 1);
        g_edge[pos] = make_uint2((unsigned)r, __float_as_uint(g_dis[r]));
    }
}

// ---------------- fused item MLP: temp = leaky(feat@W1+b1)@W2+b2 -> g_x rows ----------------
// Mainloop: block 128x256, 8 warps of 64x64, BK=32, 3-stage cp.async,
// warp-parity-staggered ks order (decollide LDS-crossbar vs tensor phases).
// Epilogue: H tile -> smem, fused 128x64x256 GEMM with W2, write to g_x.
#define G1_BM 128
#define G1_BN 256
#define G1_BK 32
#define G1_ST 3
#define G1_ASTR 36            // conflict-free A (bank = 4*lr+lc)
#define G1_BSTR 264           // conflict-free B (bank = 8*lc+lr)
#define G1_STAGE_F (G1_BM * G1_ASTR + G1_BK * G1_BSTR)   // 13056 floats
#define G1_HSTR 260           // H tile stride (260%32==4 -> bank 4*lr+lc)
#define G1_WSTR 72            // W2 stride (72%32==8 -> bank 8*lc+lr)
#define G1_EPI_F (G1_BM * G1_HSTR + HID * G1_WSTR)       // 51712 floats
#define G1_SMEM_F ((G1_ST * G1_STAGE_F) > G1_EPI_F ? (G1_ST * G1_STAGE_F) : G1_EPI_F)
#define G1_SMEM (G1_SMEM_F * 4)                          // 206848 B
#define G1_NK (FEATD / G1_BK)                            // 128

__global__ void __launch_bounds__(256)
gemm1_k(const float* __restrict__ A, const float* __restrict__ B,
        const float* __restrict__ bias, const float* __restrict__ W2,
        const float* __restrict__ b2) {
    extern __shared__ float sm[];

    int tid = threadIdx.x, lane = tid & 31, wid = tid >> 5;
    int wm0 = (wid & 1) * 64;
    int wn0 = (wid >> 1) * 64;
    int m0 = blockIdx.y * G1_BM;

    float acc[4][8][4];
#pragma unroll
    for (int i = 0; i < 4; i++)
#pragma unroll
        for (int j = 0; j < 8; j++)
#pragma unroll
            for (int k = 0; k < 4; k++) acc[i][j][k] = 0.f;

    auto loadTile = [&](int kt, int buf) {
        float* base = sm + buf * G1_STAGE_F;
#pragma unroll
        for (int i = 0; i < 4; i++) {            // A: 128x32 = 1024 vec4
            int v = tid + i * 256;
            int ar = v >> 3, ac = (v & 7) * 4;
            bool ok = (m0 + ar) < NITEM;
            cp16(&base[ar * G1_ASTR + ac],
                 A + (size_t)(m0 + ar) * FEATD + (size_t)kt * G1_BK + ac, ok);
        }
        float* bbase = base + G1_BM * G1_ASTR;
#pragma unroll
        for (int i = 0; i < 8; i++) {            // B: 32x256 = 2048 vec4
            int v = tid + i * 256;
            int br = v >> 3, bc = (v & 7) * 4 + ((wid & 7) ? 0 : 0);
            br = v >> 6; bc = (v & 63) * 4;
            cp16(&bbase[br * G1_BSTR + bc],
                 B + (size_t)(kt * G1_BK + br) * HID + bc, true);
        }
        asm volatile("cp.async.commit_group;\n");
    };

    loadTile(0, 0);
    loadTile(1, 1);

    int lr = lane >> 2, lc = lane & 3;
    int rot = (wid & 1) * 2;   // warp-parity stagger of independent ks chunks

    auto loadFrag = [&](const float* As, const float* Bs, int ks,
                        uint32_t (&fa)[4][4], uint32_t (&fb)[8][2]) {
        int k0 = ks * 8;
#pragma unroll
        for (int mf = 0; mf < 4; mf++) {
            int r = wm0 + mf * 16 + lr;
            fa[mf][0] = __float_as_uint(As[r * G1_ASTR + k0 + lc]);
            fa[mf][1] = __float_as_uint(As[(r + 8) * G1_ASTR + k0 + lc]);
            fa[mf][2] = __float_as_uint(As[r * G1_ASTR + k0 + lc + 4]);
            fa[mf][3] = __float_as_uint(As[(r + 8) * G1_ASTR + k0 + lc + 4]);
        }
#pragma unroll
        for (int nf = 0; nf < 8; nf++) {
            int c = wn0 + nf * 8 + lr;
            fb[nf][0] = __float_as_uint(Bs[(k0 + lc) * G1_BSTR + c]);
            fb[nf][1] = __float_as_uint(Bs[(k0 + lc + 4) * G1_BSTR + c]);
        }
    };

    uint32_t fa[2][4][4], fb[2][8][2];

    for (int kt = 0; kt < G1_NK; kt++) {
        int buf = kt % G1_ST;
        if (kt < G1_NK - 1) asm volatile("cp.async.wait_group 1;\n");
        else                asm volatile("cp.async.wait_group 0;\n");
        __syncthreads();
        if (kt + 2 < G1_NK) loadTile(kt + 2, (kt + 2) % G1_ST);

        const float* As = sm + buf * G1_STAGE_F;
        const float* Bs = As + G1_BM * G1_ASTR;

        loadFrag(As, Bs, rot, fa[0], fb[0]);
#pragma unroll
        for (int kss = 0; kss < 4; kss++) {
            int cur = kss & 1;
            if (kss < 3) loadFrag(As, Bs, (kss + 1 + rot) & 3, fa[cur ^ 1], fb[cur ^ 1]);
#pragma unroll
            for (int mf = 0; mf < 4; mf++)
#pragma unroll
                for (int nf = 0; nf < 8; nf++)
                    mma8(acc[mf][nf], fa[cur][mf], fb[cur][nf]);
        }
    }

    // ---- epilogue 1: H tile (bias + leaky) -> smem ----
    __syncthreads();   // everyone done with stage buffers
    float* Hs = sm;                       // [128][260]
    float* Ws = sm + G1_BM * G1_HSTR;     // [256][72]
#pragma unroll
    for (int mf = 0; mf < 4; mf++) {
#pragma unroll
        for (int nf = 0; nf < 8; nf++) {
            int cg = wn0 + nf * 8 + 2 * lc;
            float bv0 = bias[cg], bv1 = bias[cg + 1];
            int rl = wm0 + mf * 16 + lr;

            float v0 = acc[mf][nf][0] + bv0;
            float v1 = acc[mf][nf][1] + bv1;
            v0 = v0 > 0.f ? v0 : 0.01f * v0;
            v1 = v1 > 0.f ? v1 : 0.01f * v1;
            Hs[rl * G1_HSTR + cg] = v0;
            Hs[rl * G1_HSTR + cg + 1] = v1;

            float v2 = acc[mf][nf][2] + bv0;
            float v3 = acc[mf][nf][3] + bv1;
            v2 = v2 > 0.f ? v2 : 0.01f * v2;
            v3 = v3 > 0.f ? v3 : 0.01f * v3;
            Hs[(rl + 8) * G1_HSTR + cg] = v2;
            Hs[(rl + 8) * G1_HSTR + cg + 1] = v3;
        }
    }
    // load W2 [256][64] into Ws
#pragma unroll
    for (int i = 0; i < 16; i++) {
        int v = tid + i * 256;
        int wr = v >> 4, wc = (v & 15) * 4;
        cp16(&Ws[wr * G1_WSTR + wc], W2 + (size_t)wr * DIM + wc, true);
    }
    asm volatile("cp.async.commit_group;\n");
    asm volatile("cp.async.wait_group 0;\n");
    __syncthreads();

    // ---- epilogue 2: O[128x64] = H @ W2 + b2 ; warp tile 32x32 (4Mx2N) ----
    int wm2 = (wid & 3) * 32;
    int wn2 = (wid >> 2) * 32;
    float acc2[2][4][4];
#pragma unroll
    for (int i = 0; i < 2; i++)
#pragma unroll
        for (int j = 0; j < 4; j++)
#pragma unroll
            for (int k = 0; k < 4; k++) acc2[i][j][k] = 0.f;

#pragma unroll 4
    for (int kc = 0; kc < 32; kc++) {
        int k0 = kc * 8;
        uint32_t ea[2][4], eb[4][2];
#pragma unroll
        for (int mf = 0; mf < 2; mf++) {
            int r = wm2 + mf * 16 + lr;
            ea[mf][0] = __float_as_uint(Hs[r * G1_HSTR + k0 + lc]);
            ea[mf][1] = __float_as_uint(Hs[(r + 8) * G1_HSTR + k0 + lc]);
            ea[mf][2] = __float_as_uint(Hs[r * G1_HSTR + k0 + lc + 4]);
            ea[mf][3] = __float_as_uint(Hs[(r + 8) * G1_HSTR + k0 + lc + 4]);
        }
#pragma unroll
        for (int nf = 0; nf < 4; nf++) {
            int c = wn2 + nf * 8 + lr;
            eb[nf][0] = __float_as_uint(Ws[(k0 + lc) * G1_WSTR + c]);
            eb[nf][1] = __float_as_uint(Ws[(k0 + lc + 4) * G1_WSTR + c]);
        }
#pragma unroll
        for (int mf = 0; mf < 2; mf++)
#pragma unroll
            for (int nf = 0; nf < 4; nf++)
                mma8(acc2[mf][nf], ea[mf], eb[nf]);
    }

    // store into g_x item rows (offset NUSER)
#pragma unroll
    for (int mf = 0; mf < 2; mf++) {
#pragma unroll
        for (int nf = 0; nf < 4; nf++) {
            int cg = wn2 + nf * 8 + 2 * lc;
            float bv0 = b2[cg], bv1 = b2[cg + 1];
            int r = m0 + wm2 + mf * 16 + lr;
            if (r < NITEM)
                *(float2*)&g_x[(size_t)(NUSER + r) * DIM + cg] =
                    make_float2(acc2[mf][nf][0] + bv0, acc2[mf][nf][1] + bv1);
            if (r + 8 < NITEM)
                *(float2*)&g_x[(size_t)(NUSER + r + 8) * DIM + cg] =
                    make_float2(acc2[mf][nf][2] + bv0, acc2[mf][nf][3] + bv1);
        }
    }
}

// ---------------- normalize rows of x ----------------
__global__ void normalize_k(const float* __restrict__ pref) {
    int warp = (blockIdx.x * blockDim.x + threadIdx.x) >> 5;
    if (warp >= NNODE) return;
    int lane = threadIdx.x & 31;
    const float* src = (warp < NUSER) ? (pref + (size_t)warp * DIM)
                                      : (g_x + (size_t)warp * DIM);
    float v0 = src[lane], v1 = src[lane + 32];
    float s = v0 * v0 + v1 * v1;
#pragma unroll
    for (int o = 16; o; o >>= 1) s += __shfl_xor_sync(0xffffffffu, s, o);
    float inv = 1.0f / fmaxf(sqrtf(s), 1e-12f);
    g_x[(size_t)warp * DIM + lane] = v0 * inv;
    g_x[(size_t)warp * DIM + lane + 32] = v1 * inv;
}

// ---------------- warp-per-node gather convs ----------------
__global__ void gather1_k() {
    int warp = (blockIdx.x * blockDim.x + threadIdx.x) >> 5;
    if (warp >= NNODE) return;
    int lane = threadIdx.x & 31;
    int beg = g_ptr[warp], end = g_ptr[warp + 1];
    float a0 = 0.f, a1 = 0.f;
    for (int k = beg; k < end; k++) {
        uint2 e = g_edge[k];
        float c = __uint_as_float(e.y);
        const float* xs = g_x + (size_t)e.x * DIM;
        a0 += c * xs[lane];
        a1 += c * xs[lane + 32];
    }
    float dn = g_dis[warp];
    g_h[(size_t)warp * DIM + lane] = a0 * dn;
    g_h[(size_t)warp * DIM + lane + 32] = a1 * dn;
}

// conv2 fused with finalize: out = x + h + h1
__global__ void gather2_k(float* __restrict__ out) {
    int warp = (blockIdx.x * blockDim.x + threadIdx.x) >> 5;
    if (warp >= NNODE) return;
    int lane = threadIdx.x & 31;
    int beg = g_ptr[warp], end = g_ptr[warp + 1];
    float a0 = 0.f, a1 = 0.f;
    for (int k = beg; k < end; k++) {
        uint2 e = g_edge[k];
        float c = __uint_as_float(e.y);
        const float* xs = g_h + (size_t)e.x * DIM;
        a0 += c * xs[lane];
        a1 += c * xs[lane + 32];
    }
    float dn = g_dis[warp];
    size_t idx = (size_t)warp * DIM + lane;
    out[idx]      = g_x[idx]      + g_h[idx]      + a0 * dn;
    out[idx + 32] = g_x[idx + 32] + g_h[idx + 32] + a1 * dn;
}

// ---------------- host ----------------
extern "C" void kernel_launch(void* const* d_in, const int* in_sizes, int n_in,
                              void* d_out, int out_size) {
    const int*   ei   = (const int*)d_in[0];
    const float* feat = (const float*)d_in[1];
    const float* pref = (const float*)d_in[2];
    const float* W1   = (const float*)d_in[3];
    const float* b1   = (const float*)d_in[4];
    const float* W2   = (const float*)d_in[5];
    const float* b2   = (const float*)d_in[6];
    float* out = (float*)d_out;

    int E = in_sizes[0] / 2;
    const int* row = ei;
    const int* col = ei + E;

    cudaFuncSetAttribute(gemm1_k, cudaFuncAttributeMaxDynamicSharedMemorySize, G1_SMEM);

    // graph structure (+ fused MLP placed 4th so ncu's profiled slot lands on it)
    zero_k<<<(NNODE + 255) / 256, 256>>>();
    count_k<<<(E + 255) / 256, 256>>>(col, E);
    scan1_k<<<147, 1024>>>();
    gemm1_k<<<dim3(1, (NITEM + G1_BM - 1) / G1_BM), 256, G1_SMEM>>>(feat, W1, b1, W2, b2);
    scan2_k<<<1, 256>>>(147);
    scan3_k<<<147, 1024>>>();
    scatter_k<<<(E + 255) / 256, 256>>>(row, col, E);

    // normalize + 2 convs (conv2 fused with finalize)
    int warpBlocks = (NNODE * 32 + 255) / 256;
    normalize_k<<<warpBlocks, 256>>>(pref);
    gather1_k<<<warpBlocks, 256>>>();
    gather2_k<<<warpBlocks, 256>>>(out);

    // second output = preference
    if (out_size >= NNODE * DIM + NUSER * DIM) {
        cudaMemcpyAsync(out + (size_t)NNODE * DIM, pref,
                        (size_t)NUSER * DIM * sizeof(float),
                        cudaMemcpyDeviceToDevice);
    }
}

// round 11
// speedup vs baseline: 1.0998x; 1.0459x over previous
#include <cuda_runtime.h>
#include <cstdint>

#define NUSER 100000
#define NITEM 50000
#define NNODE 150000
#define DIM   64
#define FEATD 4096
#define HID   256
#define EMAX  1200000

// ---------------- scratch (device globals; no allocation allowed) ----------------
__device__ float g_x[(size_t)NNODE * DIM];     // normalized x         (38.4 MB)
__device__ float g_h[(size_t)NNODE * DIM];     // conv1
__device__ int   g_cnt[NNODE];
__device__ int   g_scan[NNODE];
__device__ int   g_ptr[NNODE + 1];
__device__ int   g_cur[NNODE];
__device__ float g_dis[NNODE];
__device__ uint2 g_edge[EMAX];                 // (src, bits(dis[src]))
__device__ int   g_bsum[256];
__device__ int   g_boff[256];

// ---------------- helpers ----------------
__device__ __forceinline__ void mma8(float* c, const uint32_t* a, const uint32_t* b) {
    asm volatile(
        "mma.sync.aligned.m16n8k8.row.col.f32.tf32.tf32.f32 "
        "{%0,%1,%2,%3},{%4,%5,%6,%7},{%8,%9},{%0,%1,%2,%3};"
        : "+f"(c[0]), "+f"(c[1]), "+f"(c[2]), "+f"(c[3])
        : "r"(a[0]), "r"(a[1]), "r"(a[2]), "r"(a[3]), "r"(b[0]), "r"(b[1]));
}

__device__ __forceinline__ void cp16(void* dst, const void* src, bool valid) {
    uint32_t d = (uint32_t)__cvta_generic_to_shared(dst);
    int sz = valid ? 16 : 0;
    asm volatile("cp.async.cg.shared.global [%0], [%1], 16, %2;\n"
                 :: "r"(d), "l"(src), "r"(sz));
}

// ---------------- graph structure ----------------
__global__ void zero_k() {
    int i = blockIdx.x * blockDim.x + threadIdx.x;
    if (i < NNODE) g_cnt[i] = 0;
}

__global__ void count_k(const int* __restrict__ col, int E) {
    int e = blockIdx.x * blockDim.x + threadIdx.x;
    if (e < E) atomicAdd(&g_cnt[col[e]], 1);
}

__global__ void scan1_k() {
    __shared__ int s[1024];
    int t = threadIdx.x;
    int i = blockIdx.x * 1024 + t;
    int v = (i < NNODE) ? g_cnt[i] : 0;
    s[t] = v;
    __syncthreads();
    for (int off = 1; off < 1024; off <<= 1) {
        int x = (t >= off) ? s[t - off] : 0;
        __syncthreads();
        s[t] += x;
        __syncthreads();
    }
    if (i < NNODE) g_scan[i] = s[t];
    if (t == 1023) g_bsum[blockIdx.x] = s[1023];
}

__global__ void scan2_k(int nb) {
    __shared__ int s[256];
    int t = threadIdx.x;
    int v = (t < nb) ? g_bsum[t] : 0;
    s[t] = v;
    __syncthreads();
    for (int off = 1; off < 256; off <<= 1) {
        int x = (t >= off) ? s[t - off] : 0;
        __syncthreads();
        s[t] += x;
        __syncthreads();
    }
    if (t < nb) g_boff[t] = s[t] - v;  // exclusive
}

__global__ void scan3_k() {
    int t = threadIdx.x;
    int i = blockIdx.x * 1024 + t;
    if (i < NNODE) {
        int c = g_cnt[i];
        int excl = g_scan[i] - c + g_boff[blockIdx.x];
        g_ptr[i] = excl;
        g_cur[i] = excl;
        g_dis[i] = (c > 0) ? rsqrtf((float)c) : 0.f;
        if (i == NNODE - 1) g_ptr[NNODE] = excl + c;
    }
}

__global__ void scatter_k(const int* __restrict__ row, const int* __restrict__ col, int E) {
    int e = blockIdx.x * blockDim.x + threadIdx.x;
    if (e < E) {
        int c = col[e], r = row[e];
        int pos = atomicAdd(&g_cur[c], 1);
        g_edge[pos] = make_uint2((unsigned)r, __float_as_uint(g_dis[r]));
    }
}

// ---------------- fused item MLP: temp = leaky(feat@W1+b1)@W2+b2 -> g_x rows ----------------
#define G1_BM 128
#define G1_BN 256
#define G1_BK 32
#define G1_ST 3
#define G1_ASTR 36            // conflict-free A (bank = 4*lr+lc)
#define G1_BSTR 264           // conflict-free B (bank = 8*lc+lr)
#define G1_STAGE_F (G1_BM * G1_ASTR + G1_BK * G1_BSTR)   // 13056 floats
#define G1_HSTR 260           // H tile stride
#define G1_WSTR 72            // W2 stride
#define G1_EPI_F (G1_BM * G1_HSTR + HID * G1_WSTR)       // 51712 floats
#define G1_SMEM_F ((G1_ST * G1_STAGE_F) > G1_EPI_F ? (G1_ST * G1_STAGE_F) : G1_EPI_F)
#define G1_SMEM (G1_SMEM_F * 4)                          // 206848 B
#define G1_NK (FEATD / G1_BK)                            // 128

__global__ void __launch_bounds__(256)
gemm1_k(const float* __restrict__ A, const float* __restrict__ B,
        const float* __restrict__ bias, const float* __restrict__ W2,
        const float* __restrict__ b2) {
    extern __shared__ float sm[];

    int tid = threadIdx.x, lane = tid & 31, wid = tid >> 5;
    int wm0 = (wid & 1) * 64;
    int wn0 = (wid >> 1) * 64;
    int m0 = blockIdx.y * G1_BM;

    float acc[4][8][4];
#pragma unroll
    for (int i = 0; i < 4; i++)
#pragma unroll
        for (int j = 0; j < 8; j++)
#pragma unroll
            for (int k = 0; k < 4; k++) acc[i][j][k] = 0.f;

    auto loadTile = [&](int kt, int buf) {
        float* base = sm + buf * G1_STAGE_F;
#pragma unroll
        for (int i = 0; i < 4; i++) {            // A: 128x32 = 1024 vec4
            int v = tid + i * 256;
            int ar = v >> 3, ac = (v & 7) * 4;
            bool ok = (m0 + ar) < NITEM;
            cp16(&base[ar * G1_ASTR + ac],
                 A + (size_t)(m0 + ar) * FEATD + (size_t)kt * G1_BK + ac, ok);
        }
        float* bbase = base + G1_BM * G1_ASTR;
#pragma unroll
        for (int i = 0; i < 8; i++) {            // B: 32x256 = 2048 vec4
            int v = tid + i * 256;
            int br = v >> 6, bc = (v & 63) * 4;
            cp16(&bbase[br * G1_BSTR + bc],
                 B + (size_t)(kt * G1_BK + br) * HID + bc, true);
        }
        asm volatile("cp.async.commit_group;\n");
    };

    loadTile(0, 0);
    loadTile(1, 1);

    int lr = lane >> 2, lc = lane & 3;
    int rot = (wid & 1) * 2;

    auto loadFrag = [&](const float* As, const float* Bs, int ks,
                        uint32_t (&fa)[4][4], uint32_t (&fb)[8][2]) {
        int k0 = ks * 8;
#pragma unroll
        for (int mf = 0; mf < 4; mf++) {
            int r = wm0 + mf * 16 + lr;
            fa[mf][0] = __float_as_uint(As[r * G1_ASTR + k0 + lc]);
            fa[mf][1] = __float_as_uint(As[(r + 8) * G1_ASTR + k0 + lc]);
            fa[mf][2] = __float_as_uint(As[r * G1_ASTR + k0 + lc + 4]);
            fa[mf][3] = __float_as_uint(As[(r + 8) * G1_ASTR + k0 + lc + 4]);
        }
#pragma unroll
        for (int nf = 0; nf < 8; nf++) {
            int c = wn0 + nf * 8 + lr;
            fb[nf][0] = __float_as_uint(Bs[(k0 + lc) * G1_BSTR + c]);
            fb[nf][1] = __float_as_uint(Bs[(k0 + lc + 4) * G1_BSTR + c]);
        }
    };

    uint32_t fa[2][4][4], fb[2][8][2];

    for (int kt = 0; kt < G1_NK; kt++) {
        int buf = kt % G1_ST;
        if (kt < G1_NK - 1) asm volatile("cp.async.wait_group 1;\n");
        else                asm volatile("cp.async.wait_group 0;\n");
        __syncthreads();
        if (kt + 2 < G1_NK) loadTile(kt + 2, (kt + 2) % G1_ST);

        const float* As = sm + buf * G1_STAGE_F;
        const float* Bs = As + G1_BM * G1_ASTR;

        loadFrag(As, Bs, rot, fa[0], fb[0]);
#pragma unroll
        for (int kss = 0; kss < 4; kss++) {
            int cur = kss & 1;
            if (kss < 3) loadFrag(As, Bs, (kss + 1 + rot) & 3, fa[cur ^ 1], fb[cur ^ 1]);
#pragma unroll
            for (int mf = 0; mf < 4; mf++)
#pragma unroll
                for (int nf = 0; nf < 8; nf++)
                    mma8(acc[mf][nf], fa[cur][mf], fb[cur][nf]);
        }
    }

    // ---- epilogue 1: H tile (bias + leaky) -> smem ----
    __syncthreads();
    float* Hs = sm;                       // [128][260]
    float* Ws = sm + G1_BM * G1_HSTR;     // [256][72]
#pragma unroll
    for (int mf = 0; mf < 4; mf++) {
#pragma unroll
        for (int nf = 0; nf < 8; nf++) {
            int cg = wn0 + nf * 8 + 2 * lc;
            float bv0 = bias[cg], bv1 = bias[cg + 1];
            int rl = wm0 + mf * 16 + lr;

            float v0 = acc[mf][nf][0] + bv0;
            float v1 = acc[mf][nf][1] + bv1;
            v0 = v0 > 0.f ? v0 : 0.01f * v0;
            v1 = v1 > 0.f ? v1 : 0.01f * v1;
            Hs[rl * G1_HSTR + cg] = v0;
            Hs[rl * G1_HSTR + cg + 1] = v1;

            float v2 = acc[mf][nf][2] + bv0;
            float v3 = acc[mf][nf][3] + bv1;
            v2 = v2 > 0.f ? v2 : 0.01f * v2;
            v3 = v3 > 0.f ? v3 : 0.01f * v3;
            Hs[(rl + 8) * G1_HSTR + cg] = v2;
            Hs[(rl + 8) * G1_HSTR + cg + 1] = v3;
        }
    }
#pragma unroll
    for (int i = 0; i < 16; i++) {
        int v = tid + i * 256;
        int wr = v >> 4, wc = (v & 15) * 4;
        cp16(&Ws[wr * G1_WSTR + wc], W2 + (size_t)wr * DIM + wc, true);
    }
    asm volatile("cp.async.commit_group;\n");
    asm volatile("cp.async.wait_group 0;\n");
    __syncthreads();

    // ---- epilogue 2: O[128x64] = H @ W2 + b2 ; warp tile 32x32 ----
    int wm2 = (wid & 3) * 32;
    int wn2 = (wid >> 2) * 32;
    float acc2[2][4][4];
#pragma unroll
    for (int i = 0; i < 2; i++)
#pragma unroll
        for (int j = 0; j < 4; j++)
#pragma unroll
            for (int k = 0; k < 4; k++) acc2[i][j][k] = 0.f;

#pragma unroll 4
    for (int kc = 0; kc < 32; kc++) {
        int k0 = kc * 8;
        uint32_t ea[2][4], eb[4][2];
#pragma unroll
        for (int mf = 0; mf < 2; mf++) {
            int r = wm2 + mf * 16 + lr;
            ea[mf][0] = __float_as_uint(Hs[r * G1_HSTR + k0 + lc]);
            ea[mf][1] = __float_as_uint(Hs[(r + 8) * G1_HSTR + k0 + lc]);
            ea[mf][2] = __float_as_uint(Hs[r * G1_HSTR + k0 + lc + 4]);
            ea[mf][3] = __float_as_uint(Hs[(r + 8) * G1_HSTR + k0 + lc + 4]);
        }
#pragma unroll
        for (int nf = 0; nf < 4; nf++) {
            int c = wn2 + nf * 8 + lr;
            eb[nf][0] = __float_as_uint(Ws[(k0 + lc) * G1_WSTR + c]);
            eb[nf][1] = __float_as_uint(Ws[(k0 + lc + 4) * G1_WSTR + c]);
        }
#pragma unroll
        for (int mf = 0; mf < 2; mf++)
#pragma unroll
            for (int nf = 0; nf < 4; nf++)
                mma8(acc2[mf][nf], ea[mf], eb[nf]);
    }

#pragma unroll
    for (int mf = 0; mf < 2; mf++) {
#pragma unroll
        for (int nf = 0; nf < 4; nf++) {
            int cg = wn2 + nf * 8 + 2 * lc;
            float bv0 = b2[cg], bv1 = b2[cg + 1];
            int r = m0 + wm2 + mf * 16 + lr;
            if (r < NITEM)
                *(float2*)&g_x[(size_t)(NUSER + r) * DIM + cg] =
                    make_float2(acc2[mf][nf][0] + bv0, acc2[mf][nf][1] + bv1);
            if (r + 8 < NITEM)
                *(float2*)&g_x[(size_t)(NUSER + r + 8) * DIM + cg] =
                    make_float2(acc2[mf][nf][2] + bv0, acc2[mf][nf][3] + bv1);
        }
    }
}

// ---------------- normalize rows of x ----------------
__global__ void normalize_k(const float* __restrict__ pref) {
    int warp = (blockIdx.x * blockDim.x + threadIdx.x) >> 5;
    if (warp >= NNODE) return;
    int lane = threadIdx.x & 31;
    const float* src = (warp < NUSER) ? (pref + (size_t)warp * DIM)
                                      : (g_x + (size_t)warp * DIM);
    float v0 = src[lane], v1 = src[lane + 32];
    float s = v0 * v0 + v1 * v1;
#pragma unroll
    for (int o = 16; o; o >>= 1) s += __shfl_xor_sync(0xffffffffu, s, o);
    float inv = 1.0f / fmaxf(sqrtf(s), 1e-12f);
    g_x[(size_t)warp * DIM + lane] = v0 * inv;
    g_x[(size_t)warp * DIM + lane + 32] = v1 * inv;
}

// ---------------- warp-per-node gather convs ----------------
__global__ void gather1_k() {
    int warp = (blockIdx.x * blockDim.x + threadIdx.x) >> 5;
    if (warp >= NNODE) return;
    int lane = threadIdx.x & 31;
    int beg = g_ptr[warp], end = g_ptr[warp + 1];
    float a0 = 0.f, a1 = 0.f;
    for (int k = beg; k < end; k++) {
        uint2 e = g_edge[k];
        float c = __uint_as_float(e.y);
        const float* xs = g_x + (size_t)e.x * DIM;
        a0 += c * xs[lane];
        a1 += c * xs[lane + 32];
    }
    float dn = g_dis[warp];
    g_h[(size_t)warp * DIM + lane] = a0 * dn;
    g_h[(size_t)warp * DIM + lane + 32] = a1 * dn;
}

// conv2 fused with finalize: out = x + h + h1
__global__ void gather2_k(float* __restrict__ out) {
    int warp = (blockIdx.x * blockDim.x + threadIdx.x) >> 5;
    if (warp >= NNODE) return;
    int lane = threadIdx.x & 31;
    int beg = g_ptr[warp], end = g_ptr[warp + 1];
    float a0 = 0.f, a1 = 0.f;
    for (int k = beg; k < end; k++) {
        uint2 e = g_edge[k];
        float c = __uint_as_float(e.y);
        const float* xs = g_h + (size_t)e.x * DIM;
        a0 += c * xs[lane];
        a1 += c * xs[lane + 32];
    }
    float dn = g_dis[warp];
    size_t idx = (size_t)warp * DIM + lane;
    out[idx]      = g_x[idx]      + g_h[idx]      + a0 * dn;
    out[idx + 32] = g_x[idx + 32] + g_h[idx + 32] + a1 * dn;
}

// ---------------- host ----------------
extern "C" void kernel_launch(void* const* d_in, const int* in_sizes, int n_in,
                              void* d_out, int out_size) {
    const int*   ei   = (const int*)d_in[0];
    const float* feat = (const float*)d_in[1];
    const float* pref = (const float*)d_in[2];
    const float* W1   = (const float*)d_in[3];
    const float* b1   = (const float*)d_in[4];
    const float* W2   = (const float*)d_in[5];
    const float* b2   = (const float*)d_in[6];
    float* out = (float*)d_out;

    int E = in_sizes[0] / 2;
    const int* row = ei;
    const int* col = ei + E;

    cudaFuncSetAttribute(gemm1_k, cudaFuncAttributeMaxDynamicSharedMemorySize, G1_SMEM);

    // Side stream for graph build (independent of the MLP GEMM).
    // Host-object creation only (no device memory). Not destroyed here:
    // destroying a stream mid-capture would invalidate the capture; the
    // handful of calls the harness makes leaks a handful of stream handles.
    cudaStream_t s2;
    cudaStreamCreateWithFlags(&s2, cudaStreamNonBlocking);
    cudaEvent_t ev0, ev1;
    cudaEventCreateWithFlags(&ev0, cudaEventDisableTiming);
    cudaEventCreateWithFlags(&ev1, cudaEventDisableTiming);

    // fork: s2 starts at graph entry
    cudaEventRecord(ev0, 0);
    cudaStreamWaitEvent(s2, ev0, 0);

    // side stream: graph structure + preference copy (all independent of gemm1)
    zero_k<<<(NNODE + 255) / 256, 256, 0, s2>>>();
    count_k<<<(E + 255) / 256, 256, 0, s2>>>(col, E);
    scan1_k<<<147, 1024, 0, s2>>>();
    scan2_k<<<1, 256, 0, s2>>>(147);
    scan3_k<<<147, 1024, 0, s2>>>();
    scatter_k<<<(E + 255) / 256, 256, 0, s2>>>(row, col, E);
    if (out_size >= NNODE * DIM + NUSER * DIM) {
        cudaMemcpyAsync(out + (size_t)NNODE * DIM, pref,
                        (size_t)NUSER * DIM * sizeof(float),
                        cudaMemcpyDeviceToDevice, s2);
    }

    // main stream: fused item MLP, then normalize (depends only on gemm1 + pref)
    gemm1_k<<<dim3(1, (NITEM + G1_BM - 1) / G1_BM), 256, G1_SMEM>>>(feat, W1, b1, W2, b2);
    int warpBlocks = (NNODE * 32 + 255) / 256;
    normalize_k<<<warpBlocks, 256>>>(pref);

    // join: gathers need scatter/scan results
    cudaEventRecord(ev1, s2);
    cudaStreamWaitEvent(0, ev1, 0);

    gather1_k<<<warpBlocks, 256>>>();
    gather2_k<<<warpBlocks, 256>>>(out);
}

// round 12
// speedup vs baseline: 1.1478x; 1.0436x over previous
#include <cuda_runtime.h>
#include <cstdint>

#define NUSER 100000
#define NITEM 50000
#define NNODE 150000
#define DIM   64
#define FEATD 4096
#define HID   256
#define EMAX  1200000

// ---------------- scratch (device globals; no allocation allowed) ----------------
__device__ float g_x[(size_t)NNODE * DIM];     // normalized x         (38.4 MB)
__device__ float g_h[(size_t)NNODE * DIM];     // conv1 output h
__device__ float g_h1u[(size_t)NUSER * DIM];   // h1 for user rows (precomputed)
__device__ int   g_cnt[NNODE];
__device__ int   g_scan[NNODE];
__device__ int   g_ptr[NNODE + 1];
__device__ int   g_cur[NNODE];
__device__ float g_dis[NNODE];
__device__ uint2 g_edge[EMAX];                 // (src, bits(dis[src]))
__device__ int   g_bsum[256];
__device__ int   g_boff[256];

// ---------------- helpers ----------------
__device__ __forceinline__ void mma8(float* c, const uint32_t* a, const uint32_t* b) {
    asm volatile(
        "mma.sync.aligned.m16n8k8.row.col.f32.tf32.tf32.f32 "
        "{%0,%1,%2,%3},{%4,%5,%6,%7},{%8,%9},{%0,%1,%2,%3};"
        : "+f"(c[0]), "+f"(c[1]), "+f"(c[2]), "+f"(c[3])
        : "r"(a[0]), "r"(a[1]), "r"(a[2]), "r"(a[3]), "r"(b[0]), "r"(b[1]));
}

__device__ __forceinline__ void cp16(void* dst, const void* src, bool valid) {
    uint32_t d = (uint32_t)__cvta_generic_to_shared(dst);
    int sz = valid ? 16 : 0;
    asm volatile("cp.async.cg.shared.global [%0], [%1], 16, %2;\n"
                 :: "r"(d), "l"(src), "r"(sz));
}

// ---------------- graph structure ----------------
__global__ void zero_k() {
    int i = blockIdx.x * blockDim.x + threadIdx.x;
    if (i < NNODE) g_cnt[i] = 0;
}

__global__ void count_k(const int* __restrict__ col, int E) {
    int e = blockIdx.x * blockDim.x + threadIdx.x;
    if (e < E) atomicAdd(&g_cnt[col[e]], 1);
}

__global__ void scan1_k() {
    __shared__ int s[1024];
    int t = threadIdx.x;
    int i = blockIdx.x * 1024 + t;
    int v = (i < NNODE) ? g_cnt[i] : 0;
    s[t] = v;
    __syncthreads();
    for (int off = 1; off < 1024; off <<= 1) {
        int x = (t >= off) ? s[t - off] : 0;
        __syncthreads();
        s[t] += x;
        __syncthreads();
    }
    if (i < NNODE) g_scan[i] = s[t];
    if (t == 1023) g_bsum[blockIdx.x] = s[1023];
}

__global__ void scan2_k(int nb) {
    __shared__ int s[256];
    int t = threadIdx.x;
    int v = (t < nb) ? g_bsum[t] : 0;
    s[t] = v;
    __syncthreads();
    for (int off = 1; off < 256; off <<= 1) {
        int x = (t >= off) ? s[t - off] : 0;
        __syncthreads();
        s[t] += x;
        __syncthreads();
    }
    if (t < nb) g_boff[t] = s[t] - v;  // exclusive
}

__global__ void scan3_k() {
    int t = threadIdx.x;
    int i = blockIdx.x * 1024 + t;
    if (i < NNODE) {
        int c = g_cnt[i];
        int excl = g_scan[i] - c + g_boff[blockIdx.x];
        g_ptr[i] = excl;
        g_cur[i] = excl;
        g_dis[i] = (c > 0) ? rsqrtf((float)c) : 0.f;
        if (i == NNODE - 1) g_ptr[NNODE] = excl + c;
    }
}

__global__ void scatter_k(const int* __restrict__ row, const int* __restrict__ col, int E) {
    int e = blockIdx.x * blockDim.x + threadIdx.x;
    if (e < E) {
        int c = col[e], r = row[e];
        int pos = atomicAdd(&g_cur[c], 1);
        g_edge[pos] = make_uint2((unsigned)r, __float_as_uint(g_dis[r]));
    }
}

// ---------------- fused item MLP + row normalize -> g_x item rows ----------------
#define G1_BM 128
#define G1_BN 256
#define G1_BK 32
#define G1_ST 3
#define G1_ASTR 36
#define G1_BSTR 264
#define G1_STAGE_F (G1_BM * G1_ASTR + G1_BK * G1_BSTR)
#define G1_HSTR 260
#define G1_WSTR 72
#define G1_OSTR 68
#define G1_EPI_F (G1_BM * G1_HSTR + HID * G1_WSTR)
#define G1_SMEM_F ((G1_ST * G1_STAGE_F) > G1_EPI_F ? (G1_ST * G1_STAGE_F) : G1_EPI_F)
#define G1_SMEM (G1_SMEM_F * 4)
#define G1_NK (FEATD / G1_BK)

__global__ void __launch_bounds__(256)
gemm1_k(const float* __restrict__ A, const float* __restrict__ B,
        const float* __restrict__ bias, const float* __restrict__ W2,
        const float* __restrict__ b2) {
    extern __shared__ float sm[];

    int tid = threadIdx.x, lane = tid & 31, wid = tid >> 5;
    int wm0 = (wid & 1) * 64;
    int wn0 = (wid >> 1) * 64;
    int m0 = blockIdx.y * G1_BM;

    float acc[4][8][4];
#pragma unroll
    for (int i = 0; i < 4; i++)
#pragma unroll
        for (int j = 0; j < 8; j++)
#pragma unroll
            for (int k = 0; k < 4; k++) acc[i][j][k] = 0.f;

    auto loadTile = [&](int kt, int buf) {
        float* base = sm + buf * G1_STAGE_F;
#pragma unroll
        for (int i = 0; i < 4; i++) {
            int v = tid + i * 256;
            int ar = v >> 3, ac = (v & 7) * 4;
            bool ok = (m0 + ar) < NITEM;
            cp16(&base[ar * G1_ASTR + ac],
                 A + (size_t)(m0 + ar) * FEATD + (size_t)kt * G1_BK + ac, ok);
        }
        float* bbase = base + G1_BM * G1_ASTR;
#pragma unroll
        for (int i = 0; i < 8; i++) {
            int v = tid + i * 256;
            int br = v >> 6, bc = (v & 63) * 4;
            cp16(&bbase[br * G1_BSTR + bc],
                 B + (size_t)(kt * G1_BK + br) * HID + bc, true);
        }
        asm volatile("cp.async.commit_group;\n");
    };

    loadTile(0, 0);
    loadTile(1, 1);

    int lr = lane >> 2, lc = lane & 3;
    int rot = (wid & 1) * 2;

    auto loadFrag = [&](const float* As, const float* Bs, int ks,
                        uint32_t (&fa)[4][4], uint32_t (&fb)[8][2]) {
        int k0 = ks * 8;
#pragma unroll
        for (int mf = 0; mf < 4; mf++) {
            int r = wm0 + mf * 16 + lr;
            fa[mf][0] = __float_as_uint(As[r * G1_ASTR + k0 + lc]);
            fa[mf][1] = __float_as_uint(As[(r + 8) * G1_ASTR + k0 + lc]);
            fa[mf][2] = __float_as_uint(As[r * G1_ASTR + k0 + lc + 4]);
            fa[mf][3] = __float_as_uint(As[(r + 8) * G1_ASTR + k0 + lc + 4]);
        }
#pragma unroll
        for (int nf = 0; nf < 8; nf++) {
            int c = wn0 + nf * 8 + lr;
            fb[nf][0] = __float_as_uint(Bs[(k0 + lc) * G1_BSTR + c]);
            fb[nf][1] = __float_as_uint(Bs[(k0 + lc + 4) * G1_BSTR + c]);
        }
    };

    uint32_t fa[2][4][4], fb[2][8][2];

    for (int kt = 0; kt < G1_NK; kt++) {
        int buf = kt % G1_ST;
        if (kt < G1_NK - 1) asm volatile("cp.async.wait_group 1;\n");
        else                asm volatile("cp.async.wait_group 0;\n");
        __syncthreads();
        if (kt + 2 < G1_NK) loadTile(kt + 2, (kt + 2) % G1_ST);

        const float* As = sm + buf * G1_STAGE_F;
        const float* Bs = As + G1_BM * G1_ASTR;

        loadFrag(As, Bs, rot, fa[0], fb[0]);
#pragma unroll
        for (int kss = 0; kss < 4; kss++) {
            int cur = kss & 1;
            if (kss < 3) loadFrag(As, Bs, (kss + 1 + rot) & 3, fa[cur ^ 1], fb[cur ^ 1]);
#pragma unroll
            for (int mf = 0; mf < 4; mf++)
#pragma unroll
                for (int nf = 0; nf < 8; nf++)
                    mma8(acc[mf][nf], fa[cur][mf], fb[cur][nf]);
        }
    }

    // ---- epilogue 1: H tile (bias + leaky) -> smem ----
    __syncthreads();
    float* Hs = sm;                       // [128][260]
    float* Ws = sm + G1_BM * G1_HSTR;     // [256][72]
#pragma unroll
    for (int mf = 0; mf < 4; mf++) {
#pragma unroll
        for (int nf = 0; nf < 8; nf++) {
            int cg = wn0 + nf * 8 + 2 * lc;
            float bv0 = bias[cg], bv1 = bias[cg + 1];
            int rl = wm0 + mf * 16 + lr;

            float v0 = acc[mf][nf][0] + bv0;
            float v1 = acc[mf][nf][1] + bv1;
            v0 = v0 > 0.f ? v0 : 0.01f * v0;
            v1 = v1 > 0.f ? v1 : 0.01f * v1;
            Hs[rl * G1_HSTR + cg] = v0;
            Hs[rl * G1_HSTR + cg + 1] = v1;

            float v2 = acc[mf][nf][2] + bv0;
            float v3 = acc[mf][nf][3] + bv1;
            v2 = v2 > 0.f ? v2 : 0.01f * v2;
            v3 = v3 > 0.f ? v3 : 0.01f * v3;
            Hs[(rl + 8) * G1_HSTR + cg] = v2;
            Hs[(rl + 8) * G1_HSTR + cg + 1] = v3;
        }
    }
#pragma unroll
    for (int i = 0; i < 16; i++) {
        int v = tid + i * 256;
        int wr = v >> 4, wc = (v & 15) * 4;
        cp16(&Ws[wr * G1_WSTR + wc], W2 + (size_t)wr * DIM + wc, true);
    }
    asm volatile("cp.async.commit_group;\n");
    asm volatile("cp.async.wait_group 0;\n");
    __syncthreads();

    // ---- epilogue 2: O[128x64] = H @ W2 + b2 ----
    int wm2 = (wid & 3) * 32;
    int wn2 = (wid >> 2) * 32;
    float acc2[2][4][4];
#pragma unroll
    for (int i = 0; i < 2; i++)
#pragma unroll
        for (int j = 0; j < 4; j++)
#pragma unroll
            for (int k = 0; k < 4; k++) acc2[i][j][k] = 0.f;

#pragma unroll 4
    for (int kc = 0; kc < 32; kc++) {
        int k0 = kc * 8;
        uint32_t ea[2][4], eb[4][2];
#pragma unroll
        for (int mf = 0; mf < 2; mf++) {
            int r = wm2 + mf * 16 + lr;
            ea[mf][0] = __float_as_uint(Hs[r * G1_HSTR + k0 + lc]);
            ea[mf][1] = __float_as_uint(Hs[(r + 8) * G1_HSTR + k0 + lc]);
            ea[mf][2] = __float_as_uint(Hs[r * G1_HSTR + k0 + lc + 4]);
            ea[mf][3] = __float_as_uint(Hs[(r + 8) * G1_HSTR + k0 + lc + 4]);
        }
#pragma unroll
        for (int nf = 0; nf < 4; nf++) {
            int c = wn2 + nf * 8 + lr;
            eb[nf][0] = __float_as_uint(Ws[(k0 + lc) * G1_WSTR + c]);
            eb[nf][1] = __float_as_uint(Ws[(k0 + lc + 4) * G1_WSTR + c]);
        }
#pragma unroll
        for (int mf = 0; mf < 2; mf++)
#pragma unroll
            for (int nf = 0; nf < 4; nf++)
                mma8(acc2[mf][nf], ea[mf], eb[nf]);
    }

    // ---- epilogue 3: stage O in smem, fused row L2-normalize -> g_x ----
    __syncthreads();
    float* Os = sm;           // [128][68]
#pragma unroll
    for (int mf = 0; mf < 2; mf++) {
#pragma unroll
        for (int nf = 0; nf < 4; nf++) {
            int cg = wn2 + nf * 8 + 2 * lc;
            float bv0 = b2[cg], bv1 = b2[cg + 1];
            int rl = wm2 + mf * 16 + lr;
            Os[rl * G1_OSTR + cg]     = acc2[mf][nf][0] + bv0;
            Os[rl * G1_OSTR + cg + 1] = acc2[mf][nf][1] + bv1;
            Os[(rl + 8) * G1_OSTR + cg]     = acc2[mf][nf][2] + bv0;
            Os[(rl + 8) * G1_OSTR + cg + 1] = acc2[mf][nf][3] + bv1;
        }
    }
    __syncthreads();
#pragma unroll
    for (int i = 0; i < 16; i++) {
        int rl = wid * 16 + i;
        int gr = m0 + rl;
        if (gr < NITEM) {
            float v0 = Os[rl * G1_OSTR + lane];
            float v1 = Os[rl * G1_OSTR + lane + 32];
            float s = v0 * v0 + v1 * v1;
#pragma unroll
            for (int o = 16; o; o >>= 1) s += __shfl_xor_sync(0xffffffffu, s, o);
            float inv = 1.0f / fmaxf(sqrtf(s), 1e-12f);
            g_x[(size_t)(NUSER + gr) * DIM + lane] = v0 * inv;
            g_x[(size_t)(NUSER + gr) * DIM + lane + 32] = v1 * inv;
        }
    }
}

// ---------------- normalize user rows (pref -> g_x) ----------------
__global__ void normalize_user_k(const float* __restrict__ pref) {
    int warp = (blockIdx.x * blockDim.x + threadIdx.x) >> 5;
    if (warp >= NUSER) return;
    int lane = threadIdx.x & 31;
    float v0 = pref[(size_t)warp * DIM + lane];
    float v1 = pref[(size_t)warp * DIM + lane + 32];
    float s = v0 * v0 + v1 * v1;
#pragma unroll
    for (int o = 16; o; o >>= 1) s += __shfl_xor_sync(0xffffffffu, s, o);
    float inv = 1.0f / fmaxf(sqrtf(s), 1e-12f);
    g_x[(size_t)warp * DIM + lane] = v0 * inv;
    g_x[(size_t)warp * DIM + lane + 32] = v1 * inv;
}

// ---------------- range gather conv ----------------
__global__ void gather_range_k(int base, int count,
                               const float* __restrict__ in, float* __restrict__ out) {
    int w = (blockIdx.x * blockDim.x + threadIdx.x) >> 5;
    if (w >= count) return;
    int node = base + w;
    int lane = threadIdx.x & 31;
    int beg = g_ptr[node], end = g_ptr[node + 1];
    float a0 = 0.f, a1 = 0.f;
    for (int k = beg; k < end; k++) {
        uint2 e = g_edge[k];
        float c = __uint_as_float(e.y);
        const float* xs = in + (size_t)e.x * DIM;
        a0 += c * xs[lane];
        a1 += c * xs[lane + 32];
    }
    float dn = g_dis[node];
    out[(size_t)node * DIM + lane] = a0 * dn;
    out[(size_t)node * DIM + lane + 32] = a1 * dn;
}

// h1 for USER rows only (sources are items; g_h item half ready)
__global__ void h1u_k() {
    int w = (blockIdx.x * blockDim.x + threadIdx.x) >> 5;
    if (w >= NUSER) return;
    int lane = threadIdx.x & 31;
    int beg = g_ptr[w], end = g_ptr[w + 1];
    float a0 = 0.f, a1 = 0.f;
    for (int k = beg; k < end; k++) {
        uint2 e = g_edge[k];
        float c = __uint_as_float(e.y);
        const float* xs = g_h + (size_t)e.x * DIM;
        a0 += c * xs[lane];
        a1 += c * xs[lane + 32];
    }
    float dn = g_dis[w];
    g_h1u[(size_t)w * DIM + lane] = a0 * dn;
    g_h1u[(size_t)w * DIM + lane + 32] = a1 * dn;
}

// final combine: out = x + h + h1
__global__ void final_k(float* __restrict__ out) {
    int n = (blockIdx.x * blockDim.x + threadIdx.x) >> 5;
    if (n >= NNODE) return;
    int lane = threadIdx.x & 31;
    float h10, h11;
    if (n < NUSER) {
        h10 = g_h1u[(size_t)n * DIM + lane];
        h11 = g_h1u[(size_t)n * DIM + lane + 32];
    } else {
        int beg = g_ptr[n], end = g_ptr[n + 1];
        float a0 = 0.f, a1 = 0.f;
        for (int k = beg; k < end; k++) {
            uint2 e = g_edge[k];
            float c = __uint_as_float(e.y);
            const float* xs = g_h + (size_t)e.x * DIM;  // sources are users
            a0 += c * xs[lane];
            a1 += c * xs[lane + 32];
        }
        float dn = g_dis[n];
        h10 = a0 * dn;
        h11 = a1 * dn;
    }
    size_t idx = (size_t)n * DIM + lane;
    out[idx]      = g_x[idx]      + g_h[idx]      + h10;
    out[idx + 32] = g_x[idx + 32] + g_h[idx + 32] + h11;
}

// ---------------- host ----------------
extern "C" void kernel_launch(void* const* d_in, const int* in_sizes, int n_in,
                              void* d_out, int out_size) {
    const int*   ei   = (const int*)d_in[0];
    const float* feat = (const float*)d_in[1];
    const float* pref = (const float*)d_in[2];
    const float* W1   = (const float*)d_in[3];
    const float* b1   = (const float*)d_in[4];
    const float* W2   = (const float*)d_in[5];
    const float* b2   = (const float*)d_in[6];
    float* out = (float*)d_out;

    int E = in_sizes[0] / 2;
    const int* row = ei;
    const int* col = ei + E;

    float *pX = nullptr, *pH = nullptr;
    cudaGetSymbolAddress((void**)&pX, g_x);
    cudaGetSymbolAddress((void**)&pH, g_h);

    cudaFuncSetAttribute(gemm1_k, cudaFuncAttributeMaxDynamicSharedMemorySize, G1_SMEM);

    // Side stream (host objects only; intentionally not destroyed mid-capture)
    cudaStream_t s2;
    cudaStreamCreateWithFlags(&s2, cudaStreamNonBlocking);
    cudaEvent_t ev0, ev1;
    cudaEventCreateWithFlags(&ev0, cudaEventDisableTiming);
    cudaEventCreateWithFlags(&ev1, cudaEventDisableTiming);

    cudaEventRecord(ev0, 0);
    cudaStreamWaitEvent(s2, ev0, 0);

    int userWarpBlocks = (NUSER * 32 + 255) / 256;
    int itemWarpBlocks = (NITEM * 32 + 255) / 256;
    int allWarpBlocks  = (NNODE * 32 + 255) / 256;

    // side stream: graph build -> user normalize -> item-half conv1 -> user h1 -> pref copy
    zero_k<<<(NNODE + 255) / 256, 256, 0, s2>>>();
    count_k<<<(E + 255) / 256, 256, 0, s2>>>(col, E);
    scan1_k<<<147, 1024, 0, s2>>>();
    scan2_k<<<1, 256, 0, s2>>>(147);
    scan3_k<<<147, 1024, 0, s2>>>();
    scatter_k<<<(E + 255) / 256, 256, 0, s2>>>(row, col, E);
    normalize_user_k<<<userWarpBlocks, 256, 0, s2>>>(pref);
    gather_range_k<<<itemWarpBlocks, 256, 0, s2>>>(NUSER, NITEM, pX, pH);  // item h (from user x)
    h1u_k<<<userWarpBlocks, 256, 0, s2>>>();                               // user h1 (from item h)
    if (out_size >= NNODE * DIM + NUSER * DIM) {
        cudaMemcpyAsync(out + (size_t)NNODE * DIM, pref,
                        (size_t)NUSER * DIM * sizeof(float),
                        cudaMemcpyDeviceToDevice, s2);
    }

    // main stream: fused item MLP + normalize (overlaps all of s2)
    gemm1_k<<<dim3(1, (NITEM + G1_BM - 1) / G1_BM), 256, G1_SMEM>>>(feat, W1, b1, W2, b2);

    // join, then gemm1-dependent half of the graph convs
    cudaEventRecord(ev1, s2);
    cudaStreamWaitEvent(0, ev1, 0);
    gather_range_k<<<userWarpBlocks, 256>>>(0, NUSER, pX, pH);  // user h (from item x)
    final_k<<<allWarpBlocks, 256>>>(out);
}